// round 15
// baseline (speedup 1.0000x reference)
#include <cuda_runtime.h>
#include <stdint.h>

// R13 skeleton (best: 77.2us), instruction-minimized mark:
//  - slot = key & MASK (no hash multiply): saves 2 instr/key; load factor
//    0.19 tolerates the weaker mixing
//  - 8 keys per thread (split-halves int4 coalescing): halves fixed overhead
//  - .cs streaming data loads, 64-bit table (EMPTY64 never aliases a
//    zero-extended 32-bit key), found bitmap + recorded slots for resolve
// Inputs are int32 (JAX x64 disabled); triple key (h*15000+r)*15000+t wraps
// in int32 == uint32 arithmetic.
#define QT_LOG2 19
#define QT_SIZE (1u << QT_LOG2)
#define QT_MASK (QT_SIZE - 1u)
#define EMPTY64 0xFFFFFFFFFFFFFFFFull
#define N_ENT 15000u
#define MAX_Q (1 << 17)

__device__ unsigned long long g_qtable[QT_SIZE];      // 4MB key table
__device__ uint32_t g_found[QT_SIZE / 32];            // 64KB found bitmap
__device__ int g_qslot[MAX_Q];

__device__ __forceinline__ uint32_t make_key(uint32_t h, uint32_t r, uint32_t t) {
    return (h * N_ENT + r) * N_ENT + t;   // wraps mod 2^32 == int32 reference
}
__device__ __forceinline__ uint32_t slot_of(uint32_t key) { return key & QT_MASK; }

__device__ __forceinline__ unsigned long long ld_cg64(const unsigned long long* p) {
    unsigned long long v;
    asm volatile("ld.global.cg.u64 %0, [%1];" : "=l"(v) : "l"(p));
    return v;
}
__device__ __forceinline__ int4 ld_cs128(const int4* p) {
    int4 v;
    asm volatile("ld.global.cs.v4.s32 {%0,%1,%2,%3}, [%4];"
                 : "=r"(v.x), "=r"(v.y), "=r"(v.z), "=r"(v.w) : "l"(p));
    return v;
}
__device__ __forceinline__ int ld_cs32(const int* p) {
    int v;
    asm volatile("ld.global.cs.s32 %0, [%1];" : "=r"(v) : "l"(p));
    return v;
}

// ---- Pass A: clear table + bitmap ----
__global__ void clear_kernel() {
    uint32_t tid = blockIdx.x * blockDim.x + threadIdx.x;
    uint32_t stride = gridDim.x * blockDim.x;
    ulonglong2* p = reinterpret_cast<ulonglong2*>(g_qtable);
    ulonglong2 v; v.x = EMPTY64; v.y = EMPTY64;
    for (uint32_t i = tid; i < QT_SIZE / 2; i += stride) p[i] = v;
    for (uint32_t i = tid; i < QT_SIZE / 32; i += stride) g_found[i] = 0u;
}

// ---- Pass B: insert query keys, record slot ----
__global__ void insert_queries_kernel(const int* __restrict__ heads,
                                      const int* __restrict__ rels,
                                      const int* __restrict__ tails, int q) {
    int i = blockIdx.x * blockDim.x + threadIdx.x;
    if (i >= q) return;
    uint32_t key = make_key((uint32_t)heads[i], (uint32_t)rels[i], (uint32_t)tails[i]);
    uint32_t slot = slot_of(key);
    while (true) {
        unsigned long long v = ld_cg64(&g_qtable[slot]);
        if (v != EMPTY64 && (uint32_t)v == key) break;      // dup
        if (v == EMPTY64) {
            unsigned long long prev =
                atomicCAS(&g_qtable[slot], EMPTY64, (unsigned long long)key);
            if (prev == EMPTY64 || (uint32_t)prev == key) break;
        }
        slot = (slot + 1) & QT_MASK;
    }
    g_qslot[i] = (int)slot;
}

// ---- Pass C: stream data, minimal-instruction probe ----
__device__ __forceinline__ void probe_mark(uint32_t key) {
    uint32_t slot = slot_of(key);
    unsigned long long v = ld_cg64(&g_qtable[slot]);
    if (v == EMPTY64) return;                 // expected: 1 load, done
    while (true) {
        if ((uint32_t)v == key) {
            atomicOr(&g_found[slot >> 5], 1u << (slot & 31));  // rare
            return;
        }
        slot = (slot + 1) & QT_MASK;
        v = ld_cg64(&g_qtable[slot]);
        if (v == EMPTY64) return;
    }
}

__global__ void mark_kernel(const int* __restrict__ data, int n8, int n) {
    int i = blockIdx.x * blockDim.x + threadIdx.x;
    if (i < n8) {
        const int4* d0 = reinterpret_cast<const int4*>(data);
        const int4* d1 = reinterpret_cast<const int4*>(data + n);
        const int4* d2 = reinterpret_cast<const int4*>(data + 2 * n);
        // split halves: int4 group i and group i+n8 (both coalesced)
        int4 ha = ld_cs128(&d0[i]),       hb = ld_cs128(&d0[i + n8]);
        int4 ra = ld_cs128(&d1[i]),       rb = ld_cs128(&d1[i + n8]);
        int4 ta = ld_cs128(&d2[i]),       tb = ld_cs128(&d2[i + n8]);
        probe_mark(make_key((uint32_t)ha.x, (uint32_t)ra.x, (uint32_t)ta.x));
        probe_mark(make_key((uint32_t)ha.y, (uint32_t)ra.y, (uint32_t)ta.y));
        probe_mark(make_key((uint32_t)ha.z, (uint32_t)ra.z, (uint32_t)ta.z));
        probe_mark(make_key((uint32_t)ha.w, (uint32_t)ra.w, (uint32_t)ta.w));
        probe_mark(make_key((uint32_t)hb.x, (uint32_t)rb.x, (uint32_t)tb.x));
        probe_mark(make_key((uint32_t)hb.y, (uint32_t)rb.y, (uint32_t)tb.y));
        probe_mark(make_key((uint32_t)hb.z, (uint32_t)rb.z, (uint32_t)tb.z));
        probe_mark(make_key((uint32_t)hb.w, (uint32_t)rb.w, (uint32_t)tb.w));
    }
    // tail: elements [8*n8, n) handled one-per-thread by the first threads
    int tail_start = n8 * 8;
    if (i < n - tail_start) {
        int ti = tail_start + i;
        probe_mark(make_key((uint32_t)ld_cs32(&data[ti]),
                            (uint32_t)ld_cs32(&data[n + ti]),
                            (uint32_t)ld_cs32(&data[2 * n + ti])));
    }
}

// ---- Pass D: resolve via recorded slot + small bitmap ----
__global__ void resolve_kernel(float* __restrict__ out, int q) {
    int i = blockIdx.x * blockDim.x + threadIdx.x;
    if (i >= q) return;
    uint32_t slot = (uint32_t)g_qslot[i];
    uint32_t w = g_found[slot >> 5];
    out[i] = ((w >> (slot & 31)) & 1u) ? 5.0f : -5.0f;
}

extern "C" void kernel_launch(void* const* d_in, const int* in_sizes, int n_in,
                              void* d_out, int out_size) {
    const int* heads = (const int*)d_in[0];
    const int* rels  = (const int*)d_in[1];
    const int* tails = (const int*)d_in[2];
    const int* data  = (const int*)d_in[3];
    float* out = (float*)d_out;

    const int q = in_sizes[0];
    const int n = in_sizes[3] / 3;
    const int n8 = n >> 3;
    const int threads = 256;

    // A: clear 4MB qtable + 64KB bitmap
    clear_kernel<<<148 * 4, threads>>>();
    // B: insert query keys + record slots
    insert_queries_kernel<<<(q + threads - 1) / threads, threads>>>(heads, rels, tails, q);
    // C: one thread per 8 keys, minimal probes
    mark_kernel<<<(n8 + threads - 1) / threads, threads>>>(data, n8, n);
    // D: write +/-5 per query from slot + bitmap
    resolve_kernel<<<(q + threads - 1) / threads, threads>>>(out, q);
}